// round 14
// baseline (speedup 1.0000x reference)
#include <cuda_runtime.h>
#include <cuda_fp16.h>
#include <cstdint>

// Problem dims (fixed by the dataset)
#define N_B 32
#define DIM 256
#define GPROT 1024   // LP/4
#define GSM   256    // LS/4
#define NHEAD 8

typedef __half hf;

// -------------------- scratch (no allocations allowed) --------------------
__device__ hf g_pgh[(size_t)N_B * GPROT * DIM];
__device__ hf g_pgl[(size_t)N_B * GPROT * DIM];
__device__ hf g_sgh[(size_t)N_B * GSM * DIM];
__device__ hf g_sgl[(size_t)N_B * GSM * DIM];
__device__ hf g_wth[5 * DIM * DIM];            // weights: single fp16
__device__ hf g_kph[(size_t)N_B * GPROT * DIM];
__device__ hf g_vph[(size_t)N_B * GPROT * DIM];
__device__ hf g_qsh[(size_t)N_B * GSM * DIM];
__device__ hf g_ksh[(size_t)N_B * GSM * DIM];
__device__ hf g_vsh[(size_t)N_B * GSM * DIM];
__device__ unsigned char g_mprot[N_B * GPROT];
__device__ unsigned char g_msm[N_B * GSM];

// -------------------- helpers --------------------
__device__ __forceinline__ unsigned smem_u32(const void* p) {
    return (unsigned)__cvta_generic_to_shared(p);
}
__device__ __forceinline__ unsigned pack_hf2(float a, float b) {
    __half2 t = __floats2half2_rn(a, b);
    return *reinterpret_cast<unsigned*>(&t);
}
__device__ __forceinline__ void split1(float v, hf& h, hf& l) {
    h = __float2half_rn(v);
    l = __float2half_rn(v - __half2float(h));
}
__device__ __forceinline__ void mma16816(float* d, const unsigned* a,
                                         unsigned b0, unsigned b1) {
    asm volatile(
        "mma.sync.aligned.m16n8k16.row.col.f32.f16.f16.f32 "
        "{%0,%1,%2,%3}, {%4,%5,%6,%7}, {%8,%9}, {%0,%1,%2,%3};\n"
        : "+f"(d[0]), "+f"(d[1]), "+f"(d[2]), "+f"(d[3])
        : "r"(a[0]), "r"(a[1]), "r"(a[2]), "r"(a[3]), "r"(b0), "r"(b1));
}
__device__ __forceinline__ void ldsm4(unsigned* r, unsigned addr) {
    asm volatile("ldmatrix.sync.aligned.m8n8.x4.shared.b16 {%0,%1,%2,%3}, [%4];"
                 : "=r"(r[0]), "=r"(r[1]), "=r"(r[2]), "=r"(r[3]) : "r"(addr));
}
__device__ __forceinline__ void ldsm4t(unsigned* r, unsigned addr) {
    asm volatile("ldmatrix.sync.aligned.m8n8.x4.trans.shared.b16 {%0,%1,%2,%3}, [%4];"
                 : "=r"(r[0]), "=r"(r[1]), "=r"(r[2]), "=r"(r[3]) : "r"(addr));
}
__device__ __forceinline__ void cpa16(unsigned dst, const void* src) {
    asm volatile("cp.async.cg.shared.global [%0], [%1], 16;"
                 :: "r"(dst), "l"(__cvta_generic_to_global(src)));
}
__device__ __forceinline__ void cp_commit() {
    asm volatile("cp.async.commit_group;" ::: "memory");
}
__device__ __forceinline__ void cp_wait1() {
    asm volatile("cp.async.wait_group 1;" ::: "memory");
}
__device__ __forceinline__ void cp_wait0() {
    asm volatile("cp.async.wait_group 0;" ::: "memory");
}

// -------------------- prep kernels (fused) --------------------
#define TPMEAN (N_B * GPROT * DIM)
#define TSMEAN (N_B * GSM * DIM)
__global__ void group_mean_all(const float* __restrict__ prot,
                               const float* __restrict__ smx,
                               hf* __restrict__ pgh, hf* __restrict__ pgl,
                               hf* __restrict__ sgh, hf* __restrict__ sgl) {
    int i = blockIdx.x * blockDim.x + threadIdx.x;
    const float* x; hf *oh, *ol; int j;
    if (i < TPMEAN) { x = prot; oh = pgh; ol = pgl; j = i; }
    else            { x = smx;  oh = sgh; ol = sgl; j = i - TPMEAN; }
    int d  = j & (DIM - 1);
    int ng = j >> 8;
    const float* p = x + (size_t)ng * 4 * DIM + d;
    float v = 0.25f * (p[0] + p[DIM] + p[2 * DIM] + p[3 * DIM]);
    split1(v, oh[j], ol[j]);
}

#define TPMASK (N_B * GPROT)
#define TSMASK (N_B * GSM)
__global__ void group_mask_all(const int* __restrict__ mprot,
                               const int* __restrict__ msm,
                               unsigned char* __restrict__ op,
                               unsigned char* __restrict__ os) {
    int i = blockIdx.x * blockDim.x + threadIdx.x;
    const int* m; unsigned char* o; int j;
    if (i < TPMASK) { m = mprot; o = op; j = i; }
    else            { m = msm;   o = os; j = i - TPMASK; }
    int4 v = *(const int4*)(m + (size_t)j * 4);
    o[j] = (unsigned char)((v.x | v.y | v.z | v.w) ? 1 : 0);
}

struct W5 { const float* p[5]; };
__global__ void wt_split_all(W5 w, hf* __restrict__ Wth) {
    int i = blockIdx.x * blockDim.x + threadIdx.x;   // 0 .. 5*65536-1
    int wi = i >> 16;
    int j  = i & 65535;
    int nr = j >> 8, k = j & 255;
    Wth[i] = __float2half_rn(w.p[wi][(size_t)k * DIM + nr]);
}

// -------------------- fp16 tensor-core GEMM (1- or 2-term A) -----------------
#define GSTG 6144u
#define GEMM_SMEM (9u * GSTG)       // AH, AL, BH x 3 stages = 55296 B

struct GemmSet { const hf* Bh; hf* Ch; int twoTerm; };
struct GemmArr { GemmSet s[3]; };

extern __shared__ char dynsmem[];

__global__ __launch_bounds__(256, 2) void gemm_bs(
    const hf* __restrict__ Ah, const hf* __restrict__ Al, GemmArr ga) {
    const GemmSet gs = ga.s[blockIdx.z];
    const unsigned sb = smem_u32(dynsmem);
    const unsigned baseAH = sb;
    const unsigned baseAL = sb + 3 * GSTG;
    const unsigned baseBH = sb + 6 * GSTG;

    const int tid = threadIdx.x, lane = tid & 31, wid = tid >> 5;
    const int g = lane >> 2, c2 = (lane & 3) * 2;
    const int bm = blockIdx.y * 128, bn = blockIdx.x * 128;
    const int wm = (wid & 3) * 32, wn = (wid >> 2) * 64;

    const int row = tid >> 1;
    const int k8  = (tid & 1) * 8;

    const int arow = ((lane >> 3) & 1) * 8 + (lane & 7);
    const int acol = ((lane >> 4) & 1) * 8;
    const int brw  = ((lane >> 4) & 1) * 8 + (lane & 7);
    const int bcl  = ((lane >> 3) & 1) * 8;
    const unsigned aAH = baseAH + (wm + arow) * 48 + acol * 2;
    const unsigned aAL = baseAL + (wm + arow) * 48 + acol * 2;
    const unsigned aBH = baseBH + (wn + brw) * 48 + bcl * 2;

    const unsigned stAh = baseAH + row * 48 + k8 * 2;
    const unsigned stAl = baseAL + row * 48 + k8 * 2;
    const unsigned stBh = baseBH + row * 48 + k8 * 2;

    float acc[2][8][4];
#pragma unroll
    for (int mi = 0; mi < 2; mi++)
#pragma unroll
        for (int ni = 0; ni < 8; ni++)
#pragma unroll
            for (int f = 0; f < 4; f++) acc[mi][ni][f] = 0.0f;

    const hf* pAh = Ah + (size_t)(bm + row) * DIM + k8;
    const hf* pAl = Al + (size_t)(bm + row) * DIM + k8;
    const hf* pBh = gs.Bh + (size_t)(bn + row) * DIM + k8;
    const int twoT = gs.twoTerm;

    cpa16(stAh, pAh); cpa16(stBh, pBh);
    if (twoT) cpa16(stAl, pAl);
    cp_commit();
    cpa16(stAh + GSTG, pAh + 16); cpa16(stBh + GSTG, pBh + 16);
    if (twoT) cpa16(stAl + GSTG, pAl + 16);
    cp_commit();

    for (int ks = 0; ks < 16; ks++) {
        if (ks == 15) cp_wait0(); else cp_wait1();
        __syncthreads();

        if (ks + 2 < 16) {
            unsigned nso = (unsigned)((ks + 2) % 3) * GSTG;
            int off = (ks + 2) * 16;
            cpa16(stAh + nso, pAh + off); cpa16(stBh + nso, pBh + off);
            if (twoT) cpa16(stAl + nso, pAl + off);
            cp_commit();
        }

        const unsigned so = (unsigned)(ks % 3) * GSTG;
        unsigned ah[2][4], al[2][4];
#pragma unroll
        for (int mi = 0; mi < 2; mi++) {
            ldsm4(ah[mi], aAH + so + mi * 16 * 48);
            if (twoT) ldsm4(al[mi], aAL + so + mi * 16 * 48);
        }
#pragma unroll
        for (int ni2 = 0; ni2 < 8; ni2 += 2) {
            unsigned bh[4];
            ldsm4(bh, aBH + so + ni2 * 8 * 48);
            mma16816(acc[0][ni2],     ah[0], bh[0], bh[1]);
            mma16816(acc[0][ni2 + 1], ah[0], bh[2], bh[3]);
            mma16816(acc[1][ni2],     ah[1], bh[0], bh[1]);
            mma16816(acc[1][ni2 + 1], ah[1], bh[2], bh[3]);
            if (twoT) {
                mma16816(acc[0][ni2],     al[0], bh[0], bh[1]);
                mma16816(acc[0][ni2 + 1], al[0], bh[2], bh[3]);
                mma16816(acc[1][ni2],     al[1], bh[0], bh[1]);
                mma16816(acc[1][ni2 + 1], al[1], bh[2], bh[3]);
            }
        }
    }

#pragma unroll
    for (int mi = 0; mi < 2; mi++) {
        int r = bm + wm + mi * 16 + g;
#pragma unroll
        for (int ni = 0; ni < 8; ni++) {
            int cn = bn + wn + ni * 8 + c2;
            *(unsigned*)&gs.Ch[(size_t)r * DIM + cn] =
                pack_hf2(acc[mi][ni][0], acc[mi][ni][1]);
            *(unsigned*)&gs.Ch[(size_t)(r + 8) * DIM + cn] =
                pack_hf2(acc[mi][ni][2], acc[mi][ni][3]);
        }
    }
}

// -------------------- fp16 flash attention (1-term S, 1-term PV) ------------
#define KVP 40
#define SSTG (64u * KVP * 2u)        // 5120B per array-stage

__global__ __launch_bounds__(256, 2) void attn_tc(
    const hf* __restrict__ Qh,
    const hf* __restrict__ Kp, const hf* __restrict__ Vp,
    const hf* __restrict__ Ks, const hf* __restrict__ Vs,
    const unsigned char* __restrict__ mprot,
    const unsigned char* __restrict__ msm,
    float* __restrict__ out) {

    const int h = blockIdx.x, n = blockIdx.y;
    const int tid = threadIdx.x, lane = tid & 31, warp = tid >> 5;
    const int g = lane >> 2, c2 = (lane & 3) * 2;

    __shared__ __align__(16) hf sKh[2][64][KVP];
    __shared__ __align__(16) hf sVh[2][64][KVP];
    __shared__ __align__(16) unsigned char sMsk[2][64];

    const int brw = ((lane >> 4) & 1) * 8 + (lane & 7);
    const int bcl = ((lane >> 3) & 1) * 8;
    const unsigned aKH = smem_u32(&sKh[0][brw][bcl]);
    const unsigned aVH = smem_u32(&sVh[0][lane & 15][(lane >> 4) * 8]);

    const int srw = tid >> 2, sch = (tid & 3) * 8;
    const unsigned dKH = smem_u32(&sKh[0][srw][sch]);
    const unsigned dVH = smem_u32(&sVh[0][srw][sch]);
    const unsigned dMsk = smem_u32(&sMsk[0][0]) + (unsigned)tid * 16;

    unsigned qfh[2][2][4];
    {
        const int r0 = warp * 32 + g;
#pragma unroll
        for (int mi = 0; mi < 2; mi++) {
            size_t base = ((size_t)n * GSM + r0 + mi * 16) * DIM + h * 32;
#pragma unroll
            for (int kc = 0; kc < 2; kc++) {
                int d0 = kc * 16 + c2;
                qfh[mi][kc][0] = *(const unsigned*)&Qh[base + d0];
                qfh[mi][kc][1] = *(const unsigned*)&Qh[base + 8 * DIM + d0];
                qfh[mi][kc][2] = *(const unsigned*)&Qh[base + d0 + 8];
                qfh[mi][kc][3] = *(const unsigned*)&Qh[base + 8 * DIM + d0 + 8];
            }
        }
    }

    for (int pass = 0; pass < 2; pass++) {
        const hf *Kb, *Vb;
        const unsigned char* Mb;
        int nt;
        if (pass == 0) {
            Kb = Kp + (size_t)n * GPROT * DIM;
            Vb = Vp + (size_t)n * GPROT * DIM;
            Mb = mprot + (size_t)n * GPROT;
            nt = GPROT / 64;
        } else {
            Kb = Ks + (size_t)n * GSM * DIM;
            Vb = Vs + (size_t)n * GSM * DIM;
            Mb = msm + (size_t)n * GSM;
            nt = GSM / 64;
        }

        float o[2][4][4];
        float srow[2][2];   // per-thread partials; lane-reduced once per pass
#pragma unroll
        for (int mi = 0; mi < 2; mi++) {
            srow[mi][0] = 0.0f; srow[mi][1] = 0.0f;
#pragma unroll
            for (int nd = 0; nd < 4; nd++)
#pragma unroll
                for (int f = 0; f < 4; f++) o[mi][nd][f] = 0.0f;
        }

        {
            size_t goff = (size_t)srw * DIM + h * 32 + sch;
            cpa16(dKH, Kb + goff);
            cpa16(dVH, Vb + goff);
            if (tid < 4) cpa16(dMsk, Mb + tid * 16);
            cp_commit();
        }

        for (int t = 0; t < nt; t++) {
            cp_wait0();
            __syncthreads();

            if (t + 1 < nt) {
                const unsigned ns = (unsigned)((t + 1) & 1);
                size_t goff = (size_t)((t + 1) * 64 + srw) * DIM + h * 32 + sch;
                cpa16(dKH + ns * SSTG, Kb + goff);
                cpa16(dVH + ns * SSTG, Vb + goff);
                if (tid < 4) cpa16(dMsk + ns * 64, Mb + (t + 1) * 64 + tid * 16);
                cp_commit();
            }

            const int cs = t & 1;
            const unsigned so = (unsigned)cs * SSTG;

#pragma unroll
            for (int mi = 0; mi < 2; mi++) {
                float sc[8][4];
#pragma unroll
                for (int ni = 0; ni < 8; ni++)
#pragma unroll
                    for (int f = 0; f < 4; f++) sc[ni][f] = 0.0f;

                // S = Qh Kh
#pragma unroll
                for (int ni2 = 0; ni2 < 8; ni2 += 2) {
                    unsigned kh[2][4];
#pragma unroll
                    for (int kc = 0; kc < 2; kc++) {
                        unsigned off = so + ni2 * 8 * (KVP * 2) + kc * 32;
                        ldsm4(kh[kc], aKH + off);
                    }
                    mma16816(sc[ni2],     qfh[mi][0], kh[0][0], kh[0][1]);
                    mma16816(sc[ni2 + 1], qfh[mi][0], kh[0][2], kh[0][3]);
                    mma16816(sc[ni2],     qfh[mi][1], kh[1][0], kh[1][1]);
                    mma16816(sc[ni2 + 1], qfh[mi][1], kh[1][2], kh[1][3]);
                }

                // fixed-shift softmax: p = exp(lg + (mask ? -10 : -1e6));
                // per-thread partial sums only (lane reduce deferred to pass end)
#pragma unroll
                for (int ni = 0; ni < 8; ni++) {
                    float a0 = sMsk[cs][ni * 8 + c2]     ? -10.0f : -1000000.0f;
                    float a1 = sMsk[cs][ni * 8 + c2 + 1] ? -10.0f : -1000000.0f;
                    sc[ni][0] = __expf(sc[ni][0] + a0);
                    sc[ni][1] = __expf(sc[ni][1] + a1);
                    sc[ni][2] = __expf(sc[ni][2] + a0);
                    sc[ni][3] = __expf(sc[ni][3] + a1);
                    srow[mi][0] += sc[ni][0] + sc[ni][1];
                    srow[mi][1] += sc[ni][2] + sc[ni][3];
                }

                // O += Ph Vh
#pragma unroll
                for (int kch = 0; kch < 4; kch++) {
                    const float* p0 = sc[2 * kch];
                    const float* p1 = sc[2 * kch + 1];
                    unsigned aH[4];
                    aH[0] = pack_hf2(p0[0], p0[1]);
                    aH[1] = pack_hf2(p0[2], p0[3]);
                    aH[2] = pack_hf2(p1[0], p1[1]);
                    aH[3] = pack_hf2(p1[2], p1[3]);
                    unsigned vh0[4], vh1[4];
                    const unsigned ob = so + kch * 16 * (KVP * 2);
                    ldsm4t(vh0, aVH + ob);        // d 0-15
                    ldsm4t(vh1, aVH + ob + 32);   // d 16-31
                    mma16816(o[mi][0], aH, vh0[0], vh0[1]);
                    mma16816(o[mi][1], aH, vh0[2], vh0[3]);
                    mma16816(o[mi][2], aH, vh1[0], vh1[1]);
                    mma16816(o[mi][3], aH, vh1[2], vh1[3]);
                }
            }
        }

        // lane-reduce srow once per pass (linear; equivalent to per-tile reduce)
#pragma unroll
        for (int mi = 0; mi < 2; mi++) {
            srow[mi][0] += __shfl_xor_sync(0xffffffffu, srow[mi][0], 1);
            srow[mi][0] += __shfl_xor_sync(0xffffffffu, srow[mi][0], 2);
            srow[mi][1] += __shfl_xor_sync(0xffffffffu, srow[mi][1], 1);
            srow[mi][1] += __shfl_xor_sync(0xffffffffu, srow[mi][1], 2);
        }

        // finish pass: normalize (guarded), apply row mask & 0.5, write/accum
        {
            const int r0 = warp * 32 + g;
#pragma unroll
            for (int mi = 0; mi < 2; mi++) {
                int r = r0 + mi * 16;
                float rm0 = msm[(size_t)n * GSM + r]     ? 0.5f : 0.0f;
                float rm1 = msm[(size_t)n * GSM + r + 8] ? 0.5f : 0.0f;
                float i0 = rm0 / fmaxf(srow[mi][0], 1e-35f);
                float i1 = rm1 / fmaxf(srow[mi][1], 1e-35f);
#pragma unroll
                for (int nd = 0; nd < 4; nd++) {
                    int col = h * 32 + nd * 8 + c2;
                    float2* po0 = (float2*)&out[((size_t)n * GSM + r) * DIM + col];
                    float2* po1 = (float2*)&out[((size_t)n * GSM + r + 8) * DIM + col];
                    float v00 = o[mi][nd][0] * i0;
                    float v01 = o[mi][nd][1] * i0;
                    float v10 = o[mi][nd][2] * i1;
                    float v11 = o[mi][nd][3] * i1;
                    if (pass == 0) {
                        *po0 = make_float2(v00, v01);
                        *po1 = make_float2(v10, v11);
                    } else {
                        float2 c0 = *po0, c1 = *po1;
                        *po0 = make_float2(c0.x + v00, c0.y + v01);
                        *po1 = make_float2(c1.x + v10, c1.y + v11);
                    }
                }
            }
        }
    }
}

// -------------------- launch --------------------
extern "C" void kernel_launch(void* const* d_in, const int* in_sizes, int n_in,
                              void* d_out, int out_size) {
    const float* protein = (const float*)d_in[0];
    const float* smx     = (const float*)d_in[1];
    const int* mask_prot = (const int*)d_in[2];
    const int* mask_sm   = (const int*)d_in[3];
    W5 w5;
    w5.p[0] = (const float*)d_in[4];   // Wk_p
    w5.p[1] = (const float*)d_in[5];   // Wv_p
    w5.p[2] = (const float*)d_in[6];   // Wq_d
    w5.p[3] = (const float*)d_in[7];   // Wk_d
    w5.p[4] = (const float*)d_in[8];   // Wv_d
    float* out = (float*)d_out;

    hf *pgh, *pgl, *sgh, *sgl, *wth;
    hf *kph, *vph, *qsh, *ksh, *vsh;
    unsigned char *mp, *ms;
    cudaGetSymbolAddress((void**)&pgh, g_pgh);
    cudaGetSymbolAddress((void**)&pgl, g_pgl);
    cudaGetSymbolAddress((void**)&sgh, g_sgh);
    cudaGetSymbolAddress((void**)&sgl, g_sgl);
    cudaGetSymbolAddress((void**)&wth, g_wth);
    cudaGetSymbolAddress((void**)&kph, g_kph);
    cudaGetSymbolAddress((void**)&vph, g_vph);
    cudaGetSymbolAddress((void**)&qsh, g_qsh);
    cudaGetSymbolAddress((void**)&ksh, g_ksh);
    cudaGetSymbolAddress((void**)&vsh, g_vsh);
    cudaGetSymbolAddress((void**)&mp, g_mprot);
    cudaGetSymbolAddress((void**)&ms, g_msm);

    cudaFuncSetAttribute(gemm_bs, cudaFuncAttributeMaxDynamicSharedMemorySize,
                         GEMM_SMEM);

    // prep
    group_mean_all<<<(TPMEAN + TSMEAN) / 256, 256>>>(protein, smx,
                                                     pgh, pgl, sgh, sgl);
    group_mask_all<<<(TPMASK + TSMASK) / 256, 256>>>(mask_prot, mask_sm, mp, ms);
    wt_split_all<<<(5 * DIM * DIM) / 256, 256>>>(w5, wth);

    // projections: K/V 1-term A (path-halved error), Q 2-term A (affects both)
    {
        GemmArr big;
        big.s[0] = {wth + 0 * DIM * DIM, kph, 0};
        big.s[1] = {wth + 1 * DIM * DIM, vph, 0};
        big.s[2] = big.s[0];
        dim3 gp(2, (N_B * GPROT) / 128, 2);
        gemm_bs<<<gp, 256, GEMM_SMEM>>>(pgh, pgl, big);

        GemmArr sml;
        sml.s[0] = {wth + 2 * DIM * DIM, qsh, 1};
        sml.s[1] = {wth + 3 * DIM * DIM, ksh, 0};
        sml.s[2] = {wth + 4 * DIM * DIM, vsh, 0};
        dim3 gs(2, (N_B * GSM) / 128, 3);
        gemm_bs<<<gs, 256, GEMM_SMEM>>>(sgh, sgl, sml);
    }

    // attention
    {
        dim3 ga(NHEAD, N_B);
        attn_tc<<<ga, 256>>>(qsh, kph, vph, ksh, vsh, mp, ms, out);
    }
}

// round 15
// speedup vs baseline: 1.2026x; 1.2026x over previous
#include <cuda_runtime.h>
#include <cuda_fp16.h>
#include <cstdint>

// Problem dims (fixed by the dataset)
#define N_B 32
#define DIM 256
#define GPROT 1024   // LP/4
#define GSM   256    // LS/4
#define NHEAD 8

typedef __half hf;

// -------------------- scratch (no allocations allowed) --------------------
__device__ hf g_pgh[(size_t)N_B * GPROT * DIM];
__device__ hf g_pgl[(size_t)N_B * GPROT * DIM];
__device__ hf g_sgh[(size_t)N_B * GSM * DIM];
__device__ hf g_sgl[(size_t)N_B * GSM * DIM];
__device__ hf g_wth[5 * DIM * DIM];            // weights: single fp16
__device__ hf g_kph[(size_t)N_B * GPROT * DIM];
__device__ hf g_vph[(size_t)N_B * GPROT * DIM];
__device__ hf g_qsh[(size_t)N_B * GSM * DIM];
__device__ hf g_ksh[(size_t)N_B * GSM * DIM];
__device__ hf g_vsh[(size_t)N_B * GSM * DIM];
__device__ unsigned char g_mprot[N_B * GPROT];
__device__ unsigned char g_msm[N_B * GSM];

// -------------------- helpers --------------------
__device__ __forceinline__ unsigned smem_u32(const void* p) {
    return (unsigned)__cvta_generic_to_shared(p);
}
__device__ __forceinline__ unsigned pack_hf2(float a, float b) {
    __half2 t = __floats2half2_rn(a, b);
    return *reinterpret_cast<unsigned*>(&t);
}
__device__ __forceinline__ void split1(float v, hf& h, hf& l) {
    h = __float2half_rn(v);
    l = __float2half_rn(v - __half2float(h));
}
__device__ __forceinline__ void mma16816(float* d, const unsigned* a,
                                         unsigned b0, unsigned b1) {
    asm volatile(
        "mma.sync.aligned.m16n8k16.row.col.f32.f16.f16.f32 "
        "{%0,%1,%2,%3}, {%4,%5,%6,%7}, {%8,%9}, {%0,%1,%2,%3};\n"
        : "+f"(d[0]), "+f"(d[1]), "+f"(d[2]), "+f"(d[3])
        : "r"(a[0]), "r"(a[1]), "r"(a[2]), "r"(a[3]), "r"(b0), "r"(b1));
}
__device__ __forceinline__ void ldsm4(unsigned* r, unsigned addr) {
    asm volatile("ldmatrix.sync.aligned.m8n8.x4.shared.b16 {%0,%1,%2,%3}, [%4];"
                 : "=r"(r[0]), "=r"(r[1]), "=r"(r[2]), "=r"(r[3]) : "r"(addr));
}
__device__ __forceinline__ void ldsm4t(unsigned* r, unsigned addr) {
    asm volatile("ldmatrix.sync.aligned.m8n8.x4.trans.shared.b16 {%0,%1,%2,%3}, [%4];"
                 : "=r"(r[0]), "=r"(r[1]), "=r"(r[2]), "=r"(r[3]) : "r"(addr));
}
__device__ __forceinline__ void cpa16(unsigned dst, const void* src) {
    asm volatile("cp.async.cg.shared.global [%0], [%1], 16;"
                 :: "r"(dst), "l"(__cvta_generic_to_global(src)));
}
__device__ __forceinline__ void cp_commit() {
    asm volatile("cp.async.commit_group;" ::: "memory");
}
__device__ __forceinline__ void cp_wait1() {
    asm volatile("cp.async.wait_group 1;" ::: "memory");
}
__device__ __forceinline__ void cp_wait0() {
    asm volatile("cp.async.wait_group 0;" ::: "memory");
}

// -------------------- prep kernels (fused) --------------------
#define TPMEAN (N_B * GPROT * DIM)
#define TSMEAN (N_B * GSM * DIM)
__global__ void group_mean_all(const float* __restrict__ prot,
                               const float* __restrict__ smx,
                               hf* __restrict__ pgh, hf* __restrict__ pgl,
                               hf* __restrict__ sgh, hf* __restrict__ sgl) {
    int i = blockIdx.x * blockDim.x + threadIdx.x;
    const float* x; hf *oh, *ol; int j;
    if (i < TPMEAN) { x = prot; oh = pgh; ol = pgl; j = i; }
    else            { x = smx;  oh = sgh; ol = sgl; j = i - TPMEAN; }
    int d  = j & (DIM - 1);
    int ng = j >> 8;
    const float* p = x + (size_t)ng * 4 * DIM + d;
    float v = 0.25f * (p[0] + p[DIM] + p[2 * DIM] + p[3 * DIM]);
    split1(v, oh[j], ol[j]);
}

#define TPMASK (N_B * GPROT)
#define TSMASK (N_B * GSM)
__global__ void group_mask_all(const int* __restrict__ mprot,
                               const int* __restrict__ msm,
                               unsigned char* __restrict__ op,
                               unsigned char* __restrict__ os) {
    int i = blockIdx.x * blockDim.x + threadIdx.x;
    const int* m; unsigned char* o; int j;
    if (i < TPMASK) { m = mprot; o = op; j = i; }
    else            { m = msm;   o = os; j = i - TPMASK; }
    int4 v = *(const int4*)(m + (size_t)j * 4);
    o[j] = (unsigned char)((v.x | v.y | v.z | v.w) ? 1 : 0);
}

struct W5 { const float* p[5]; };
__global__ void wt_split_all(W5 w, hf* __restrict__ Wth) {
    int i = blockIdx.x * blockDim.x + threadIdx.x;   // 0 .. 5*65536-1
    int wi = i >> 16;
    int j  = i & 65535;
    int nr = j >> 8, k = j & 255;
    Wth[i] = __float2half_rn(w.p[wi][(size_t)k * DIM + nr]);
}

// -------------------- gemm_2t: 2-term A (Q projection), slab 16 -------------
// Exactly the proven R13 structure: 32 MMAs/warp/slab, 3-stage cp.async.
#define GSTG 6144u
#define GEMM2_SMEM (9u * GSTG)       // AH, AL, BH x 3 stages = 55296 B

extern __shared__ char dynsmem[];

__global__ __launch_bounds__(256, 2) void gemm_2t(
    const hf* __restrict__ Ah, const hf* __restrict__ Al,
    const hf* __restrict__ Bh, hf* __restrict__ Ch) {
    const unsigned sb = smem_u32(dynsmem);
    const unsigned baseAH = sb;
    const unsigned baseAL = sb + 3 * GSTG;
    const unsigned baseBH = sb + 6 * GSTG;

    const int tid = threadIdx.x, lane = tid & 31, wid = tid >> 5;
    const int g = lane >> 2, c2 = (lane & 3) * 2;
    const int bm = blockIdx.y * 128, bn = blockIdx.x * 128;
    const int wm = (wid & 3) * 32, wn = (wid >> 2) * 64;

    const int row = tid >> 1;
    const int k8  = (tid & 1) * 8;

    const int arow = ((lane >> 3) & 1) * 8 + (lane & 7);
    const int acol = ((lane >> 4) & 1) * 8;
    const int brw  = ((lane >> 4) & 1) * 8 + (lane & 7);
    const int bcl  = ((lane >> 3) & 1) * 8;
    const unsigned aAH = baseAH + (wm + arow) * 48 + acol * 2;
    const unsigned aAL = baseAL + (wm + arow) * 48 + acol * 2;
    const unsigned aBH = baseBH + (wn + brw) * 48 + bcl * 2;

    const unsigned stAh = baseAH + row * 48 + k8 * 2;
    const unsigned stAl = baseAL + row * 48 + k8 * 2;
    const unsigned stBh = baseBH + row * 48 + k8 * 2;

    float acc[2][8][4];
#pragma unroll
    for (int mi = 0; mi < 2; mi++)
#pragma unroll
        for (int ni = 0; ni < 8; ni++)
#pragma unroll
            for (int f = 0; f < 4; f++) acc[mi][ni][f] = 0.0f;

    const hf* pAh = Ah + (size_t)(bm + row) * DIM + k8;
    const hf* pAl = Al + (size_t)(bm + row) * DIM + k8;
    const hf* pBh = Bh + (size_t)(bn + row) * DIM + k8;

    cpa16(stAh, pAh); cpa16(stAl, pAl); cpa16(stBh, pBh);
    cp_commit();
    cpa16(stAh + GSTG, pAh + 16); cpa16(stAl + GSTG, pAl + 16);
    cpa16(stBh + GSTG, pBh + 16);
    cp_commit();

    for (int ks = 0; ks < 16; ks++) {
        if (ks == 15) cp_wait0(); else cp_wait1();
        __syncthreads();

        if (ks + 2 < 16) {
            unsigned nso = (unsigned)((ks + 2) % 3) * GSTG;
            int off = (ks + 2) * 16;
            cpa16(stAh + nso, pAh + off); cpa16(stAl + nso, pAl + off);
            cpa16(stBh + nso, pBh + off);
            cp_commit();
        }

        const unsigned so = (unsigned)(ks % 3) * GSTG;
        unsigned ah[2][4], al[2][4];
#pragma unroll
        for (int mi = 0; mi < 2; mi++) {
            ldsm4(ah[mi], aAH + so + mi * 16 * 48);
            ldsm4(al[mi], aAL + so + mi * 16 * 48);
        }
#pragma unroll
        for (int ni2 = 0; ni2 < 8; ni2 += 2) {
            unsigned bh[4];
            ldsm4(bh, aBH + so + ni2 * 8 * 48);
            mma16816(acc[0][ni2],     ah[0], bh[0], bh[1]);
            mma16816(acc[0][ni2 + 1], ah[0], bh[2], bh[3]);
            mma16816(acc[1][ni2],     ah[1], bh[0], bh[1]);
            mma16816(acc[1][ni2 + 1], ah[1], bh[2], bh[3]);
            mma16816(acc[0][ni2],     al[0], bh[0], bh[1]);
            mma16816(acc[0][ni2 + 1], al[0], bh[2], bh[3]);
            mma16816(acc[1][ni2],     al[1], bh[0], bh[1]);
            mma16816(acc[1][ni2 + 1], al[1], bh[2], bh[3]);
        }
    }

#pragma unroll
    for (int mi = 0; mi < 2; mi++) {
        int r = bm + wm + mi * 16 + g;
#pragma unroll
        for (int ni = 0; ni < 8; ni++) {
            int cn = bn + wn + ni * 8 + c2;
            *(unsigned*)&Ch[(size_t)r * DIM + cn] =
                pack_hf2(acc[mi][ni][0], acc[mi][ni][1]);
            *(unsigned*)&Ch[(size_t)(r + 8) * DIM + cn] =
                pack_hf2(acc[mi][ni][2], acc[mi][ni][3]);
        }
    }
}

// -------------------- gemm_1t: 1-term A (K/V projections), slab 32 ----------
// Same per-stage compute density as gemm_2t (32 MMAs/warp/slab), 8 slabs.
#define G1P 40u                        // smem pitch (fp16) -> 80B rows
#define G1STG (128u * G1P * 2u)        // 10240 B per array-stage
#define GEMM1_SMEM (6u * G1STG)        // AH, BH x 3 stages = 61440 B

struct GemmSet1 { const hf* Bh; hf* Ch; };
struct GemmArr1 { GemmSet1 s[2]; };

__global__ __launch_bounds__(256, 2) void gemm_1t(
    const hf* __restrict__ Ah, GemmArr1 ga) {
    const GemmSet1 gs = ga.s[blockIdx.z];
    const unsigned sb = smem_u32(dynsmem);
    const unsigned baseAH = sb;
    const unsigned baseBH = sb + 3 * G1STG;

    const int tid = threadIdx.x, lane = tid & 31, wid = tid >> 5;
    const int g = lane >> 2, c2 = (lane & 3) * 2;
    const int bm = blockIdx.y * 128, bn = blockIdx.x * 128;
    const int wm = (wid & 3) * 32, wn = (wid >> 2) * 64;

    // staging: 2 x 16B chunks per thread per array (128 rows x 64B)
    const int r0c = tid >> 1;                 // chunk-pair row: (tid*2)>>2
    const int c0c = (tid & 1) * 16;           // fp16 col of first chunk: 0 or 16
    // chunks: (r0c, c0c) and (r0c, c0c+8)
    const unsigned stA0 = baseAH + r0c * (G1P * 2) + c0c * 2;
    const unsigned stB0 = baseBH + r0c * (G1P * 2) + c0c * 2;

    const int arow = ((lane >> 3) & 1) * 8 + (lane & 7);
    const int acol = ((lane >> 4) & 1) * 8;
    const int brw  = ((lane >> 4) & 1) * 8 + (lane & 7);
    const int bcl  = ((lane >> 3) & 1) * 8;
    const unsigned aAH = baseAH + (wm + arow) * (G1P * 2) + acol * 2;
    const unsigned aBH = baseBH + (wn + brw) * (G1P * 2) + bcl * 2;

    float acc[2][8][4];
#pragma unroll
    for (int mi = 0; mi < 2; mi++)
#pragma unroll
        for (int ni = 0; ni < 8; ni++)
#pragma unroll
            for (int f = 0; f < 4; f++) acc[mi][ni][f] = 0.0f;

    const hf* pA = Ah + (size_t)(bm + r0c) * DIM + c0c;
    const hf* pB = gs.Bh + (size_t)(bn + r0c) * DIM + c0c;

    // prologue: slabs 0,1 -> stages 0,1
#pragma unroll
    for (int s = 0; s < 2; s++) {
        unsigned so = (unsigned)s * G1STG;
        int off = s * 32;
        cpa16(stA0 + so, pA + off);      cpa16(stA0 + so + 16, pA + off + 8);
        cpa16(stB0 + so, pB + off);      cpa16(stB0 + so + 16, pB + off + 8);
        cp_commit();
    }

    for (int ks = 0; ks < 8; ks++) {
        if (ks == 7) cp_wait0(); else cp_wait1();
        __syncthreads();

        if (ks + 2 < 8) {
            unsigned nso = (unsigned)((ks + 2) % 3) * G1STG;
            int off = (ks + 2) * 32;
            cpa16(stA0 + nso, pA + off);     cpa16(stA0 + nso + 16, pA + off + 8);
            cpa16(stB0 + nso, pB + off);     cpa16(stB0 + nso + 16, pB + off + 8);
            cp_commit();
        }

        const unsigned so = (unsigned)(ks % 3) * G1STG;
        unsigned ah[2][2][4];   // [mi][kc]
#pragma unroll
        for (int mi = 0; mi < 2; mi++)
#pragma unroll
            for (int kc = 0; kc < 2; kc++)
                ldsm4(ah[mi][kc], aAH + so + mi * 16 * (G1P * 2) + kc * 32);
#pragma unroll
        for (int ni2 = 0; ni2 < 8; ni2 += 2) {
            unsigned bh0[4], bh1[4];
            ldsm4(bh0, aBH + so + ni2 * 8 * (G1P * 2));
            ldsm4(bh1, aBH + so + ni2 * 8 * (G1P * 2) + 32);
            mma16816(acc[0][ni2],     ah[0][0], bh0[0], bh0[1]);
            mma16816(acc[0][ni2 + 1], ah[0][0], bh0[2], bh0[3]);
            mma16816(acc[1][ni2],     ah[1][0], bh0[0], bh0[1]);
            mma16816(acc[1][ni2 + 1], ah[1][0], bh0[2], bh0[3]);
            mma16816(acc[0][ni2],     ah[0][1], bh1[0], bh1[1]);
            mma16816(acc[0][ni2 + 1], ah[0][1], bh1[2], bh1[3]);
            mma16816(acc[1][ni2],     ah[1][1], bh1[0], bh1[1]);
            mma16816(acc[1][ni2 + 1], ah[1][1], bh1[2], bh1[3]);
        }
    }

#pragma unroll
    for (int mi = 0; mi < 2; mi++) {
        int r = bm + wm + mi * 16 + g;
#pragma unroll
        for (int ni = 0; ni < 8; ni++) {
            int cn = bn + wn + ni * 8 + c2;
            *(unsigned*)&gs.Ch[(size_t)r * DIM + cn] =
                pack_hf2(acc[mi][ni][0], acc[mi][ni][1]);
            *(unsigned*)&gs.Ch[(size_t)(r + 8) * DIM + cn] =
                pack_hf2(acc[mi][ni][2], acc[mi][ni][3]);
        }
    }
}

// -------------------- fp16 flash attention (1-term S, 1-term PV) ------------
#define KVP 40
#define SSTG (64u * KVP * 2u)        // 5120B per array-stage

__global__ __launch_bounds__(256, 2) void attn_tc(
    const hf* __restrict__ Qh,
    const hf* __restrict__ Kp, const hf* __restrict__ Vp,
    const hf* __restrict__ Ks, const hf* __restrict__ Vs,
    const unsigned char* __restrict__ mprot,
    const unsigned char* __restrict__ msm,
    float* __restrict__ out) {

    const int h = blockIdx.x, n = blockIdx.y;
    const int tid = threadIdx.x, lane = tid & 31, warp = tid >> 5;
    const int g = lane >> 2, c2 = (lane & 3) * 2;

    __shared__ __align__(16) hf sKh[2][64][KVP];
    __shared__ __align__(16) hf sVh[2][64][KVP];
    __shared__ __align__(16) unsigned char sMsk[2][64];

    const int brw = ((lane >> 4) & 1) * 8 + (lane & 7);
    const int bcl = ((lane >> 3) & 1) * 8;
    const unsigned aKH = smem_u32(&sKh[0][brw][bcl]);
    const unsigned aVH = smem_u32(&sVh[0][lane & 15][(lane >> 4) * 8]);

    const int srw = tid >> 2, sch = (tid & 3) * 8;
    const unsigned dKH = smem_u32(&sKh[0][srw][sch]);
    const unsigned dVH = smem_u32(&sVh[0][srw][sch]);
    const unsigned dMsk = smem_u32(&sMsk[0][0]) + (unsigned)tid * 16;

    unsigned qfh[2][2][4];
    {
        const int r0 = warp * 32 + g;
#pragma unroll
        for (int mi = 0; mi < 2; mi++) {
            size_t base = ((size_t)n * GSM + r0 + mi * 16) * DIM + h * 32;
#pragma unroll
            for (int kc = 0; kc < 2; kc++) {
                int d0 = kc * 16 + c2;
                qfh[mi][kc][0] = *(const unsigned*)&Qh[base + d0];
                qfh[mi][kc][1] = *(const unsigned*)&Qh[base + 8 * DIM + d0];
                qfh[mi][kc][2] = *(const unsigned*)&Qh[base + d0 + 8];
                qfh[mi][kc][3] = *(const unsigned*)&Qh[base + 8 * DIM + d0 + 8];
            }
        }
    }

    for (int pass = 0; pass < 2; pass++) {
        const hf *Kb, *Vb;
        const unsigned char* Mb;
        int nt;
        if (pass == 0) {
            Kb = Kp + (size_t)n * GPROT * DIM;
            Vb = Vp + (size_t)n * GPROT * DIM;
            Mb = mprot + (size_t)n * GPROT;
            nt = GPROT / 64;
        } else {
            Kb = Ks + (size_t)n * GSM * DIM;
            Vb = Vs + (size_t)n * GSM * DIM;
            Mb = msm + (size_t)n * GSM;
            nt = GSM / 64;
        }

        float o[2][4][4];
        float srow[2][2];   // per-thread partials; lane-reduced once per pass
#pragma unroll
        for (int mi = 0; mi < 2; mi++) {
            srow[mi][0] = 0.0f; srow[mi][1] = 0.0f;
#pragma unroll
            for (int nd = 0; nd < 4; nd++)
#pragma unroll
                for (int f = 0; f < 4; f++) o[mi][nd][f] = 0.0f;
        }

        {
            size_t goff = (size_t)srw * DIM + h * 32 + sch;
            cpa16(dKH, Kb + goff);
            cpa16(dVH, Vb + goff);
            if (tid < 4) cpa16(dMsk, Mb + tid * 16);
            cp_commit();
        }

        for (int t = 0; t < nt; t++) {
            cp_wait0();
            __syncthreads();

            if (t + 1 < nt) {
                const unsigned ns = (unsigned)((t + 1) & 1);
                size_t goff = (size_t)((t + 1) * 64 + srw) * DIM + h * 32 + sch;
                cpa16(dKH + ns * SSTG, Kb + goff);
                cpa16(dVH + ns * SSTG, Vb + goff);
                if (tid < 4) cpa16(dMsk + ns * 64, Mb + (t + 1) * 64 + tid * 16);
                cp_commit();
            }

            const int cs = t & 1;
            const unsigned so = (unsigned)cs * SSTG;

#pragma unroll
            for (int mi = 0; mi < 2; mi++) {
                float sc[8][4];
#pragma unroll
                for (int ni = 0; ni < 8; ni++)
#pragma unroll
                    for (int f = 0; f < 4; f++) sc[ni][f] = 0.0f;

                // S = Qh Kh
#pragma unroll
                for (int ni2 = 0; ni2 < 8; ni2 += 2) {
                    unsigned kh[2][4];
#pragma unroll
                    for (int kc = 0; kc < 2; kc++) {
                        unsigned off = so + ni2 * 8 * (KVP * 2) + kc * 32;
                        ldsm4(kh[kc], aKH + off);
                    }
                    mma16816(sc[ni2],     qfh[mi][0], kh[0][0], kh[0][1]);
                    mma16816(sc[ni2 + 1], qfh[mi][0], kh[0][2], kh[0][3]);
                    mma16816(sc[ni2],     qfh[mi][1], kh[1][0], kh[1][1]);
                    mma16816(sc[ni2 + 1], qfh[mi][1], kh[1][2], kh[1][3]);
                }

                // fixed-shift softmax: p = exp(lg + (mask ? -10 : -1e6))
#pragma unroll
                for (int ni = 0; ni < 8; ni++) {
                    float a0 = sMsk[cs][ni * 8 + c2]     ? -10.0f : -1000000.0f;
                    float a1 = sMsk[cs][ni * 8 + c2 + 1] ? -10.0f : -1000000.0f;
                    sc[ni][0] = __expf(sc[ni][0] + a0);
                    sc[ni][1] = __expf(sc[ni][1] + a1);
                    sc[ni][2] = __expf(sc[ni][2] + a0);
                    sc[ni][3] = __expf(sc[ni][3] + a1);
                    srow[mi][0] += sc[ni][0] + sc[ni][1];
                    srow[mi][1] += sc[ni][2] + sc[ni][3];
                }

                // O += Ph Vh
#pragma unroll
                for (int kch = 0; kch < 4; kch++) {
                    const float* p0 = sc[2 * kch];
                    const float* p1 = sc[2 * kch + 1];
                    unsigned aH[4];
                    aH[0] = pack_hf2(p0[0], p0[1]);
                    aH[1] = pack_hf2(p0[2], p0[3]);
                    aH[2] = pack_hf2(p1[0], p1[1]);
                    aH[3] = pack_hf2(p1[2], p1[3]);
                    unsigned vh0[4], vh1[4];
                    const unsigned ob = so + kch * 16 * (KVP * 2);
                    ldsm4t(vh0, aVH + ob);        // d 0-15
                    ldsm4t(vh1, aVH + ob + 32);   // d 16-31
                    mma16816(o[mi][0], aH, vh0[0], vh0[1]);
                    mma16816(o[mi][1], aH, vh0[2], vh0[3]);
                    mma16816(o[mi][2], aH, vh1[0], vh1[1]);
                    mma16816(o[mi][3], aH, vh1[2], vh1[3]);
                }
            }
        }

        // lane-reduce srow once per pass
#pragma unroll
        for (int mi = 0; mi < 2; mi++) {
            srow[mi][0] += __shfl_xor_sync(0xffffffffu, srow[mi][0], 1);
            srow[mi][0] += __shfl_xor_sync(0xffffffffu, srow[mi][0], 2);
            srow[mi][1] += __shfl_xor_sync(0xffffffffu, srow[mi][1], 1);
            srow[mi][1] += __shfl_xor_sync(0xffffffffu, srow[mi][1], 2);
        }

        // finish pass: normalize (guarded), apply row mask & 0.5, write/accum
        {
            const int r0 = warp * 32 + g;
#pragma unroll
            for (int mi = 0; mi < 2; mi++) {
                int r = r0 + mi * 16;
                float rm0 = msm[(size_t)n * GSM + r]     ? 0.5f : 0.0f;
                float rm1 = msm[(size_t)n * GSM + r + 8] ? 0.5f : 0.0f;
                float i0 = rm0 / fmaxf(srow[mi][0], 1e-35f);
                float i1 = rm1 / fmaxf(srow[mi][1], 1e-35f);
#pragma unroll
                for (int nd = 0; nd < 4; nd++) {
                    int col = h * 32 + nd * 8 + c2;
                    float2* po0 = (float2*)&out[((size_t)n * GSM + r) * DIM + col];
                    float2* po1 = (float2*)&out[((size_t)n * GSM + r + 8) * DIM + col];
                    float v00 = o[mi][nd][0] * i0;
                    float v01 = o[mi][nd][1] * i0;
                    float v10 = o[mi][nd][2] * i1;
                    float v11 = o[mi][nd][3] * i1;
                    if (pass == 0) {
                        *po0 = make_float2(v00, v01);
                        *po1 = make_float2(v10, v11);
                    } else {
                        float2 c0 = *po0, c1 = *po1;
                        *po0 = make_float2(c0.x + v00, c0.y + v01);
                        *po1 = make_float2(c1.x + v10, c1.y + v11);
                    }
                }
            }
        }
    }
}

// -------------------- launch --------------------
extern "C" void kernel_launch(void* const* d_in, const int* in_sizes, int n_in,
                              void* d_out, int out_size) {
    const float* protein = (const float*)d_in[0];
    const float* smx     = (const float*)d_in[1];
    const int* mask_prot = (const int*)d_in[2];
    const int* mask_sm   = (const int*)d_in[3];
    W5 w5;
    w5.p[0] = (const float*)d_in[4];   // Wk_p
    w5.p[1] = (const float*)d_in[5];   // Wv_p
    w5.p[2] = (const float*)d_in[6];   // Wq_d
    w5.p[3] = (const float*)d_in[7];   // Wk_d
    w5.p[4] = (const float*)d_in[8];   // Wv_d
    float* out = (float*)d_out;

    hf *pgh, *pgl, *sgh, *sgl, *wth;
    hf *kph, *vph, *qsh, *ksh, *vsh;
    unsigned char *mp, *ms;
    cudaGetSymbolAddress((void**)&pgh, g_pgh);
    cudaGetSymbolAddress((void**)&pgl, g_pgl);
    cudaGetSymbolAddress((void**)&sgh, g_sgh);
    cudaGetSymbolAddress((void**)&sgl, g_sgl);
    cudaGetSymbolAddress((void**)&wth, g_wth);
    cudaGetSymbolAddress((void**)&kph, g_kph);
    cudaGetSymbolAddress((void**)&vph, g_vph);
    cudaGetSymbolAddress((void**)&qsh, g_qsh);
    cudaGetSymbolAddress((void**)&ksh, g_ksh);
    cudaGetSymbolAddress((void**)&vsh, g_vsh);
    cudaGetSymbolAddress((void**)&mp, g_mprot);
    cudaGetSymbolAddress((void**)&ms, g_msm);

    cudaFuncSetAttribute(gemm_2t, cudaFuncAttributeMaxDynamicSharedMemorySize,
                         GEMM2_SMEM);
    cudaFuncSetAttribute(gemm_1t, cudaFuncAttributeMaxDynamicSharedMemorySize,
                         GEMM1_SMEM);

    // prep
    group_mean_all<<<(TPMEAN + TSMEAN) / 256, 256>>>(protein, smx,
                                                     pgh, pgl, sgh, sgl);
    group_mask_all<<<(TPMASK + TSMASK) / 256, 256>>>(mask_prot, mask_sm, mp, ms);
    wt_split_all<<<(5 * DIM * DIM) / 256, 256>>>(w5, wth);

    // projections: K/V via 1-term (slab-32) kernel; Q via 2-term kernel
    {
        GemmArr1 big;
        big.s[0] = {wth + 0 * DIM * DIM, kph};
        big.s[1] = {wth + 1 * DIM * DIM, vph};
        dim3 gp(2, (N_B * GPROT) / 128, 2);
        gemm_1t<<<gp, 256, GEMM1_SMEM>>>(pgh, big);

        GemmArr1 sml;
        sml.s[0] = {wth + 3 * DIM * DIM, ksh};
        sml.s[1] = {wth + 4 * DIM * DIM, vsh};
        dim3 gs(2, (N_B * GSM) / 128, 2);
        gemm_1t<<<gs, 256, GEMM1_SMEM>>>(sgh, sml);

        dim3 gq(2, (N_B * GSM) / 128, 1);
        gemm_2t<<<gq, 256, GEMM2_SMEM>>>(sgh, sgl, wth + 2 * DIM * DIM, qsh);
    }

    // attention
    {
        dim3 ga(NHEAD, N_B);
        attn_tc<<<ga, 256>>>(qsh, kph, vph, ksh, vsh, mp, ms, out);
    }
}

// round 17
// speedup vs baseline: 1.2331x; 1.0253x over previous
#include <cuda_runtime.h>
#include <cuda_fp16.h>
#include <cstdint>

// Problem dims (fixed by the dataset)
#define N_B 32
#define DIM 256
#define GPROT 1024   // LP/4
#define GSM   256    // LS/4
#define NHEAD 8

typedef __half hf;

// -------------------- scratch (no allocations allowed) --------------------
__device__ hf g_pgh[(size_t)N_B * GPROT * DIM];
__device__ hf g_pgl[(size_t)N_B * GPROT * DIM];
__device__ hf g_sgh[(size_t)N_B * GSM * DIM];
__device__ hf g_sgl[(size_t)N_B * GSM * DIM];
__device__ hf g_wth[5 * DIM * DIM];            // weights: single fp16
__device__ hf g_kph[(size_t)N_B * GPROT * DIM];
__device__ hf g_vph[(size_t)N_B * GPROT * DIM];
__device__ hf g_qsh[(size_t)N_B * GSM * DIM];
__device__ hf g_ksh[(size_t)N_B * GSM * DIM];
__device__ hf g_vsh[(size_t)N_B * GSM * DIM];
__device__ unsigned char g_mprot[N_B * GPROT];
__device__ unsigned char g_msm[N_B * GSM];

// -------------------- helpers --------------------
__device__ __forceinline__ unsigned smem_u32(const void* p) {
    return (unsigned)__cvta_generic_to_shared(p);
}
__device__ __forceinline__ unsigned pack_hf2(float a, float b) {
    __half2 t = __floats2half2_rn(a, b);
    return *reinterpret_cast<unsigned*>(&t);
}
__device__ __forceinline__ void split1(float v, hf& h, hf& l) {
    h = __float2half_rn(v);
    l = __float2half_rn(v - __half2float(h));
}
__device__ __forceinline__ void mma16816(float* d, const unsigned* a,
                                         unsigned b0, unsigned b1) {
    asm volatile(
        "mma.sync.aligned.m16n8k16.row.col.f32.f16.f16.f32 "
        "{%0,%1,%2,%3}, {%4,%5,%6,%7}, {%8,%9}, {%0,%1,%2,%3};\n"
        : "+f"(d[0]), "+f"(d[1]), "+f"(d[2]), "+f"(d[3])
        : "r"(a[0]), "r"(a[1]), "r"(a[2]), "r"(a[3]), "r"(b0), "r"(b1));
}
__device__ __forceinline__ void ldsm4(unsigned* r, unsigned addr) {
    asm volatile("ldmatrix.sync.aligned.m8n8.x4.shared.b16 {%0,%1,%2,%3}, [%4];"
                 : "=r"(r[0]), "=r"(r[1]), "=r"(r[2]), "=r"(r[3]) : "r"(addr));
}
__device__ __forceinline__ void ldsm4t(unsigned* r, unsigned addr) {
    asm volatile("ldmatrix.sync.aligned.m8n8.x4.trans.shared.b16 {%0,%1,%2,%3}, [%4];"
                 : "=r"(r[0]), "=r"(r[1]), "=r"(r[2]), "=r"(r[3]) : "r"(addr));
}
__device__ __forceinline__ void cpa16(unsigned dst, const void* src) {
    asm volatile("cp.async.cg.shared.global [%0], [%1], 16;"
                 :: "r"(dst), "l"(__cvta_generic_to_global(src)));
}
__device__ __forceinline__ void cp_commit() {
    asm volatile("cp.async.commit_group;" ::: "memory");
}
__device__ __forceinline__ void cp_wait1() {
    asm volatile("cp.async.wait_group 1;" ::: "memory");
}
__device__ __forceinline__ void cp_wait0() {
    asm volatile("cp.async.wait_group 0;" ::: "memory");
}

// -------------------- prep kernels (fused) --------------------
#define TPMEAN (N_B * GPROT * DIM)
#define TSMEAN (N_B * GSM * DIM)
__global__ void group_mean_all(const float* __restrict__ prot,
                               const float* __restrict__ smx,
                               hf* __restrict__ pgh, hf* __restrict__ pgl,
                               hf* __restrict__ sgh, hf* __restrict__ sgl) {
    int i = blockIdx.x * blockDim.x + threadIdx.x;
    const float* x; hf *oh, *ol; int j;
    if (i < TPMEAN) { x = prot; oh = pgh; ol = pgl; j = i; }
    else            { x = smx;  oh = sgh; ol = sgl; j = i - TPMEAN; }
    int d  = j & (DIM - 1);
    int ng = j >> 8;
    const float* p = x + (size_t)ng * 4 * DIM + d;
    float v = 0.25f * (p[0] + p[DIM] + p[2 * DIM] + p[3 * DIM]);
    split1(v, oh[j], ol[j]);
}

#define TPMASK (N_B * GPROT)
#define TSMASK (N_B * GSM)
__global__ void group_mask_all(const int* __restrict__ mprot,
                               const int* __restrict__ msm,
                               unsigned char* __restrict__ op,
                               unsigned char* __restrict__ os) {
    int i = blockIdx.x * blockDim.x + threadIdx.x;
    const int* m; unsigned char* o; int j;
    if (i < TPMASK) { m = mprot; o = op; j = i; }
    else            { m = msm;   o = os; j = i - TPMASK; }
    int4 v = *(const int4*)(m + (size_t)j * 4);
    o[j] = (unsigned char)((v.x | v.y | v.z | v.w) ? 1 : 0);
}

struct W5 { const float* p[5]; };
__global__ void wt_split_all(W5 w, hf* __restrict__ Wth) {
    int i = blockIdx.x * blockDim.x + threadIdx.x;   // 0 .. 5*65536-1
    int wi = i >> 16;
    int j  = i & 65535;
    int nr = j >> 8, k = j & 255;
    Wth[i] = __float2half_rn(w.p[wi][(size_t)k * DIM + nr]);
}

// -------------------- gemm_2t: 2-term A (Q projection), slab 16 -------------
#define GSTG 6144u
#define GEMM2_SMEM (9u * GSTG)       // AH, AL, BH x 3 stages = 55296 B

extern __shared__ char dynsmem[];

__global__ __launch_bounds__(256, 2) void gemm_2t(
    const hf* __restrict__ Ah, const hf* __restrict__ Al,
    const hf* __restrict__ Bh, hf* __restrict__ Ch) {
    const unsigned sb = smem_u32(dynsmem);
    const unsigned baseAH = sb;
    const unsigned baseAL = sb + 3 * GSTG;
    const unsigned baseBH = sb + 6 * GSTG;

    const int tid = threadIdx.x, lane = tid & 31, wid = tid >> 5;
    const int g = lane >> 2, c2 = (lane & 3) * 2;
    const int bm = blockIdx.y * 128, bn = blockIdx.x * 128;
    const int wm = (wid & 3) * 32, wn = (wid >> 2) * 64;

    const int row = tid >> 1;
    const int k8  = (tid & 1) * 8;

    const int arow = ((lane >> 3) & 1) * 8 + (lane & 7);
    const int acol = ((lane >> 4) & 1) * 8;
    const int brw  = ((lane >> 4) & 1) * 8 + (lane & 7);
    const int bcl  = ((lane >> 3) & 1) * 8;
    const unsigned aAH = baseAH + (wm + arow) * 48 + acol * 2;
    const unsigned aAL = baseAL + (wm + arow) * 48 + acol * 2;
    const unsigned aBH = baseBH + (wn + brw) * 48 + bcl * 2;

    const unsigned stAh = baseAH + row * 48 + k8 * 2;
    const unsigned stAl = baseAL + row * 48 + k8 * 2;
    const unsigned stBh = baseBH + row * 48 + k8 * 2;

    float acc[2][8][4];
#pragma unroll
    for (int mi = 0; mi < 2; mi++)
#pragma unroll
        for (int ni = 0; ni < 8; ni++)
#pragma unroll
            for (int f = 0; f < 4; f++) acc[mi][ni][f] = 0.0f;

    const hf* pAh = Ah + (size_t)(bm + row) * DIM + k8;
    const hf* pAl = Al + (size_t)(bm + row) * DIM + k8;
    const hf* pBh = Bh + (size_t)(bn + row) * DIM + k8;

    cpa16(stAh, pAh); cpa16(stAl, pAl); cpa16(stBh, pBh);
    cp_commit();
    cpa16(stAh + GSTG, pAh + 16); cpa16(stAl + GSTG, pAl + 16);
    cpa16(stBh + GSTG, pBh + 16);
    cp_commit();

    for (int ks = 0; ks < 16; ks++) {
        if (ks == 15) cp_wait0(); else cp_wait1();
        __syncthreads();

        if (ks + 2 < 16) {
            unsigned nso = (unsigned)((ks + 2) % 3) * GSTG;
            int off = (ks + 2) * 16;
            cpa16(stAh + nso, pAh + off); cpa16(stAl + nso, pAl + off);
            cpa16(stBh + nso, pBh + off);
            cp_commit();
        }

        const unsigned so = (unsigned)(ks % 3) * GSTG;
        unsigned ah[2][4], al[2][4];
#pragma unroll
        for (int mi = 0; mi < 2; mi++) {
            ldsm4(ah[mi], aAH + so + mi * 16 * 48);
            ldsm4(al[mi], aAL + so + mi * 16 * 48);
        }
#pragma unroll
        for (int ni2 = 0; ni2 < 8; ni2 += 2) {
            unsigned bh[4];
            ldsm4(bh, aBH + so + ni2 * 8 * 48);
            mma16816(acc[0][ni2],     ah[0], bh[0], bh[1]);
            mma16816(acc[0][ni2 + 1], ah[0], bh[2], bh[3]);
            mma16816(acc[1][ni2],     ah[1], bh[0], bh[1]);
            mma16816(acc[1][ni2 + 1], ah[1], bh[2], bh[3]);
            mma16816(acc[0][ni2],     al[0], bh[0], bh[1]);
            mma16816(acc[0][ni2 + 1], al[0], bh[2], bh[3]);
            mma16816(acc[1][ni2],     al[1], bh[0], bh[1]);
            mma16816(acc[1][ni2 + 1], al[1], bh[2], bh[3]);
        }
    }

#pragma unroll
    for (int mi = 0; mi < 2; mi++) {
        int r = bm + wm + mi * 16 + g;
#pragma unroll
        for (int ni = 0; ni < 8; ni++) {
            int cn = bn + wn + ni * 8 + c2;
            *(unsigned*)&Ch[(size_t)r * DIM + cn] =
                pack_hf2(acc[mi][ni][0], acc[mi][ni][1]);
            *(unsigned*)&Ch[(size_t)(r + 8) * DIM + cn] =
                pack_hf2(acc[mi][ni][2], acc[mi][ni][3]);
        }
    }
}

// -------------------- gemm_1t: 1-term A, slab 32, merged work list ----------
#define G1P 40u                        // smem pitch (fp16) -> 80B rows
#define G1STG (128u * G1P * 2u)        // 10240 B per array-stage
#define GEMM1_SMEM (6u * G1STG)        // AH, BH x 3 stages = 61440 B

struct G1Args {
    const hf* Abig; const hf* Asml;
    const hf* B[4]; hf* C[4];
};

__global__ __launch_bounds__(256, 2) void gemm_1t(G1Args ga) {
    const int byr = blockIdx.y, z = blockIdx.z;
    const hf* Ah; int bm, idx;
    if (byr < 256) { Ah = ga.Abig; bm = byr * 128;        idx = z; }
    else           { Ah = ga.Asml; bm = (byr - 256) * 128; idx = 2 + z; }
    const hf* Bh = ga.B[idx];
    hf* Ch = ga.C[idx];

    const unsigned sb = smem_u32(dynsmem);
    const unsigned baseAH = sb;
    const unsigned baseBH = sb + 3 * G1STG;

    const int tid = threadIdx.x, lane = tid & 31, wid = tid >> 5;
    const int g = lane >> 2, c2 = (lane & 3) * 2;
    const int bn = blockIdx.x * 128;
    const int wm = (wid & 3) * 32, wn = (wid >> 2) * 64;

    const int r0c = tid >> 1;
    const int c0c = (tid & 1) * 16;
    const unsigned stA0 = baseAH + r0c * (G1P * 2) + c0c * 2;
    const unsigned stB0 = baseBH + r0c * (G1P * 2) + c0c * 2;

    const int arow = ((lane >> 3) & 1) * 8 + (lane & 7);
    const int acol = ((lane >> 4) & 1) * 8;
    const int brw  = ((lane >> 4) & 1) * 8 + (lane & 7);
    const int bcl  = ((lane >> 3) & 1) * 8;
    const unsigned aAH = baseAH + (wm + arow) * (G1P * 2) + acol * 2;
    const unsigned aBH = baseBH + (wn + brw) * (G1P * 2) + bcl * 2;

    float acc[2][8][4];
#pragma unroll
    for (int mi = 0; mi < 2; mi++)
#pragma unroll
        for (int ni = 0; ni < 8; ni++)
#pragma unroll
            for (int f = 0; f < 4; f++) acc[mi][ni][f] = 0.0f;

    const hf* pA = Ah + (size_t)(bm + r0c) * DIM + c0c;
    const hf* pB = Bh + (size_t)(bn + r0c) * DIM + c0c;

#pragma unroll
    for (int s = 0; s < 2; s++) {
        unsigned so = (unsigned)s * G1STG;
        int off = s * 32;
        cpa16(stA0 + so, pA + off);      cpa16(stA0 + so + 16, pA + off + 8);
        cpa16(stB0 + so, pB + off);      cpa16(stB0 + so + 16, pB + off + 8);
        cp_commit();
    }

    for (int ks = 0; ks < 8; ks++) {
        if (ks == 7) cp_wait0(); else cp_wait1();
        __syncthreads();

        if (ks + 2 < 8) {
            unsigned nso = (unsigned)((ks + 2) % 3) * G1STG;
            int off = (ks + 2) * 32;
            cpa16(stA0 + nso, pA + off);     cpa16(stA0 + nso + 16, pA + off + 8);
            cpa16(stB0 + nso, pB + off);     cpa16(stB0 + nso + 16, pB + off + 8);
            cp_commit();
        }

        const unsigned so = (unsigned)(ks % 3) * G1STG;
        unsigned ah[2][2][4];
#pragma unroll
        for (int mi = 0; mi < 2; mi++)
#pragma unroll
            for (int kc = 0; kc < 2; kc++)
                ldsm4(ah[mi][kc], aAH + so + mi * 16 * (G1P * 2) + kc * 32);
#pragma unroll
        for (int ni2 = 0; ni2 < 8; ni2 += 2) {
            unsigned bh0[4], bh1[4];
            ldsm4(bh0, aBH + so + ni2 * 8 * (G1P * 2));
            ldsm4(bh1, aBH + so + ni2 * 8 * (G1P * 2) + 32);
            mma16816(acc[0][ni2],     ah[0][0], bh0[0], bh0[1]);
            mma16816(acc[0][ni2 + 1], ah[0][0], bh0[2], bh0[3]);
            mma16816(acc[1][ni2],     ah[1][0], bh0[0], bh0[1]);
            mma16816(acc[1][ni2 + 1], ah[1][0], bh0[2], bh0[3]);
            mma16816(acc[0][ni2],     ah[0][1], bh1[0], bh1[1]);
            mma16816(acc[0][ni2 + 1], ah[0][1], bh1[2], bh1[3]);
            mma16816(acc[1][ni2],     ah[1][1], bh1[0], bh1[1]);
            mma16816(acc[1][ni2 + 1], ah[1][1], bh1[2], bh1[3]);
        }
    }

#pragma unroll
    for (int mi = 0; mi < 2; mi++) {
        int r = bm + wm + mi * 16 + g;
#pragma unroll
        for (int ni = 0; ni < 8; ni++) {
            int cn = bn + wn + ni * 8 + c2;
            *(unsigned*)&Ch[(size_t)r * DIM + cn] =
                pack_hf2(acc[mi][ni][0], acc[mi][ni][1]);
            *(unsigned*)&Ch[(size_t)(r + 8) * DIM + cn] =
                pack_hf2(acc[mi][ni][2], acc[mi][ni][3]);
        }
    }
}

// -------------------- fp16 flash attention ----------------------------------
// 1-term S, fp32 __expf fixed-shift softmax, PV with ones-column MMA sum.
#define KPX 40                        // K smem pitch
#define VPX 56                        // V smem pitch (cols 32.. hold ones/zeros)
#define KSTG (64u * KPX * 2u)         // 5120 B
#define VSTG (64u * VPX * 2u)         // 7168 B

__global__ __launch_bounds__(256, 2) void attn_tc(
    const hf* __restrict__ Qh,
    const hf* __restrict__ Kp, const hf* __restrict__ Vp,
    const hf* __restrict__ Ks, const hf* __restrict__ Vs,
    const unsigned char* __restrict__ mprot,
    const unsigned char* __restrict__ msm,
    float* __restrict__ out) {

    const int h = blockIdx.x, n = blockIdx.y;
    const int tid = threadIdx.x, lane = tid & 31, warp = tid >> 5;
    const int g = lane >> 2, c2 = (lane & 3) * 2;

    __shared__ __align__(16) hf sKh[2][64][KPX];
    __shared__ __align__(16) hf sVh[2][64][VPX];
    __shared__ __align__(16) unsigned char sMsk[2][64];

    const int brw = ((lane >> 4) & 1) * 8 + (lane & 7);
    const int bcl = ((lane >> 3) & 1) * 8;
    const unsigned aKH = smem_u32(&sKh[0][brw][bcl]);
    const unsigned aVH = smem_u32(&sVh[0][lane & 15][(lane >> 4) * 8]);

    const int srw = tid >> 2, sch = (tid & 3) * 8;
    const unsigned dKH = smem_u32(&sKh[0][srw][sch]);
    const unsigned dVH = smem_u32(&sVh[0][srw][sch]);
    const unsigned dMsk = smem_u32(&sMsk[0][0]) + (unsigned)tid * 16;

    // init V cols 32..55: col 32 = 1.0 (sum column), rest 0. Written once;
    // cp.async only ever touches cols 0..31.
    if (tid < 128) {
        int s = tid >> 6, r = tid & 63;
        sVh[s][r][32] = __float2half(1.0f);
#pragma unroll
        for (int j = 33; j < VPX; j++) sVh[s][r][j] = __float2half(0.0f);
    }

    unsigned qfh[2][2][4];
    {
        const int r0 = warp * 32 + g;
#pragma unroll
        for (int mi = 0; mi < 2; mi++) {
            size_t base = ((size_t)n * GSM + r0 + mi * 16) * DIM + h * 32;
#pragma unroll
            for (int kc = 0; kc < 2; kc++) {
                int d0 = kc * 16 + c2;
                qfh[mi][kc][0] = *(const unsigned*)&Qh[base + d0];
                qfh[mi][kc][1] = *(const unsigned*)&Qh[base + 8 * DIM + d0];
                qfh[mi][kc][2] = *(const unsigned*)&Qh[base + d0 + 8];
                qfh[mi][kc][3] = *(const unsigned*)&Qh[base + 8 * DIM + d0 + 8];
            }
        }
    }

    for (int pass = 0; pass < 2; pass++) {
        const hf *Kb, *Vb;
        const unsigned char* Mb;
        int nt;
        if (pass == 0) {
            Kb = Kp + (size_t)n * GPROT * DIM;
            Vb = Vp + (size_t)n * GPROT * DIM;
            Mb = mprot + (size_t)n * GPROT;
            nt = GPROT / 64;
        } else {
            Kb = Ks + (size_t)n * GSM * DIM;
            Vb = Vs + (size_t)n * GSM * DIM;
            Mb = msm + (size_t)n * GSM;
            nt = GSM / 64;
        }

        float o[2][5][4];   // [4] = ones-column accumulator (row sums)
#pragma unroll
        for (int mi = 0; mi < 2; mi++)
#pragma unroll
            for (int nd = 0; nd < 5; nd++)
#pragma unroll
                for (int f = 0; f < 4; f++) o[mi][nd][f] = 0.0f;

        {
            size_t goff = (size_t)srw * DIM + h * 32 + sch;
            cpa16(dKH, Kb + goff);
            cpa16(dVH, Vb + goff);
            if (tid < 4) cpa16(dMsk, Mb + tid * 16);
            cp_commit();
        }

        for (int t = 0; t < nt; t++) {
            cp_wait0();
            __syncthreads();

            if (t + 1 < nt) {
                const unsigned ns = (unsigned)((t + 1) & 1);
                size_t goff = (size_t)((t + 1) * 64 + srw) * DIM + h * 32 + sch;
                cpa16(dKH + ns * KSTG, Kb + goff);
                cpa16(dVH + ns * VSTG, Vb + goff);
                if (tid < 4) cpa16(dMsk + ns * 64, Mb + (t + 1) * 64 + tid * 16);
                cp_commit();
            }

            const int cs = t & 1;
            const unsigned kso = (unsigned)cs * KSTG;
            const unsigned vso = (unsigned)cs * VSTG;

#pragma unroll
            for (int mi = 0; mi < 2; mi++) {
                float sc[8][4];
#pragma unroll
                for (int ni = 0; ni < 8; ni++)
#pragma unroll
                    for (int f = 0; f < 4; f++) sc[ni][f] = 0.0f;

                // S = Qh Kh
#pragma unroll
                for (int ni2 = 0; ni2 < 8; ni2 += 2) {
                    unsigned kh[2][4];
#pragma unroll
                    for (int kc = 0; kc < 2; kc++) {
                        unsigned off = kso + ni2 * 8 * (KPX * 2) + kc * 32;
                        ldsm4(kh[kc], aKH + off);
                    }
                    mma16816(sc[ni2],     qfh[mi][0], kh[0][0], kh[0][1]);
                    mma16816(sc[ni2 + 1], qfh[mi][0], kh[0][2], kh[0][3]);
                    mma16816(sc[ni2],     qfh[mi][1], kh[1][0], kh[1][1]);
                    mma16816(sc[ni2 + 1], qfh[mi][1], kh[1][2], kh[1][3]);
                }

                // p = exp(lg + (mask ? -10 : -1e6)) in fp32 (argument precision
                // matters: fp16-exp args failed in R16), then pack to fp16 frags
                unsigned pp[8][2];
#pragma unroll
                for (int ni = 0; ni < 8; ni++) {
                    float a0 = sMsk[cs][ni * 8 + c2]     ? -10.0f : -1000000.0f;
                    float a1 = sMsk[cs][ni * 8 + c2 + 1] ? -10.0f : -1000000.0f;
                    pp[ni][0] = pack_hf2(__expf(sc[ni][0] + a0),
                                         __expf(sc[ni][1] + a1));
                    pp[ni][1] = pack_hf2(__expf(sc[ni][2] + a0),
                                         __expf(sc[ni][3] + a1));
                }

                // O += P V ; fifth n-tile (cols 32-39) is the ones column -> sums
#pragma unroll
                for (int kch = 0; kch < 4; kch++) {
                    unsigned aH[4];
                    aH[0] = pp[2 * kch][0];
                    aH[1] = pp[2 * kch][1];
                    aH[2] = pp[2 * kch + 1][0];
                    aH[3] = pp[2 * kch + 1][1];
                    unsigned vh0[4], vh1[4], vh2[4];
                    const unsigned ob = vso + kch * 16 * (VPX * 2);
                    ldsm4t(vh0, aVH + ob);        // d 0-15
                    ldsm4t(vh1, aVH + ob + 32);   // d 16-31
                    ldsm4t(vh2, aVH + ob + 64);   // cols 32-47 (ones at 32)
                    mma16816(o[mi][0], aH, vh0[0], vh0[1]);
                    mma16816(o[mi][1], aH, vh0[2], vh0[3]);
                    mma16816(o[mi][2], aH, vh1[0], vh1[1]);
                    mma16816(o[mi][3], aH, vh1[2], vh1[3]);
                    mma16816(o[mi][4], aH, vh2[0], vh2[1]);
                }
            }
        }

        // finish pass: row sums live in o[mi][4] col 32 (quad lane 0, f0/f2)
        {
            const int r0 = warp * 32 + g;
#pragma unroll
            for (int mi = 0; mi < 2; mi++) {
                int r = r0 + mi * 16;
                float s0 = __shfl_sync(0xffffffffu, o[mi][4][0], lane & 28);
                float s1 = __shfl_sync(0xffffffffu, o[mi][4][2], lane & 28);
                float rm0 = msm[(size_t)n * GSM + r]     ? 0.5f : 0.0f;
                float rm1 = msm[(size_t)n * GSM + r + 8] ? 0.5f : 0.0f;
                float i0 = rm0 / fmaxf(s0, 1e-35f);
                float i1 = rm1 / fmaxf(s1, 1e-35f);
#pragma unroll
                for (int nd = 0; nd < 4; nd++) {
                    int col = h * 32 + nd * 8 + c2;
                    float2* po0 = (float2*)&out[((size_t)n * GSM + r) * DIM + col];
                    float2* po1 = (float2*)&out[((size_t)n * GSM + r + 8) * DIM + col];
                    float v00 = o[mi][nd][0] * i0;
                    float v01 = o[mi][nd][1] * i0;
                    float v10 = o[mi][nd][2] * i1;
                    float v11 = o[mi][nd][3] * i1;
                    if (pass == 0) {
                        *po0 = make_float2(v00, v01);
                        *po1 = make_float2(v10, v11);
                    } else {
                        float2 c0 = *po0, c1 = *po1;
                        *po0 = make_float2(c0.x + v00, c0.y + v01);
                        *po1 = make_float2(c1.x + v10, c1.y + v11);
                    }
                }
            }
        }
    }
}

// -------------------- launch --------------------
extern "C" void kernel_launch(void* const* d_in, const int* in_sizes, int n_in,
                              void* d_out, int out_size) {
    const float* protein = (const float*)d_in[0];
    const float* smx     = (const float*)d_in[1];
    const int* mask_prot = (const int*)d_in[2];
    const int* mask_sm   = (const int*)d_in[3];
    W5 w5;
    w5.p[0] = (const float*)d_in[4];   // Wk_p
    w5.p[1] = (const float*)d_in[5];   // Wv_p
    w5.p[2] = (const float*)d_in[6];   // Wq_d
    w5.p[3] = (const float*)d_in[7];   // Wk_d
    w5.p[4] = (const float*)d_in[8];   // Wv_d
    float* out = (float*)d_out;

    hf *pgh, *pgl, *sgh, *sgl, *wth;
    hf *kph, *vph, *qsh, *ksh, *vsh;
    unsigned char *mp, *ms;
    cudaGetSymbolAddress((void**)&pgh, g_pgh);
    cudaGetSymbolAddress((void**)&pgl, g_pgl);
    cudaGetSymbolAddress((void**)&sgh, g_sgh);
    cudaGetSymbolAddress((void**)&sgl, g_sgl);
    cudaGetSymbolAddress((void**)&wth, g_wth);
    cudaGetSymbolAddress((void**)&kph, g_kph);
    cudaGetSymbolAddress((void**)&vph, g_vph);
    cudaGetSymbolAddress((void**)&qsh, g_qsh);
    cudaGetSymbolAddress((void**)&ksh, g_ksh);
    cudaGetSymbolAddress((void**)&vsh, g_vsh);
    cudaGetSymbolAddress((void**)&mp, g_mprot);
    cudaGetSymbolAddress((void**)&ms, g_msm);

    cudaFuncSetAttribute(gemm_2t, cudaFuncAttributeMaxDynamicSharedMemorySize,
                         GEMM2_SMEM);
    cudaFuncSetAttribute(gemm_1t, cudaFuncAttributeMaxDynamicSharedMemorySize,
                         GEMM1_SMEM);

    // prep
    group_mean_all<<<(TPMEAN + TSMEAN) / 256, 256>>>(protein, smx,
                                                     pgh, pgl, sgh, sgl);
    group_mask_all<<<(TPMASK + TSMASK) / 256, 256>>>(mask_prot, mask_sm, mp, ms);
    wt_split_all<<<(5 * DIM * DIM) / 256, 256>>>(w5, wth);

    // projections: all four K/V in ONE merged 1-term launch; Q 2-term
    {
        G1Args ga;
        ga.Abig = pgh; ga.Asml = sgh;
        ga.B[0] = wth + 0 * DIM * DIM;  ga.C[0] = kph;
        ga.B[1] = wth + 1 * DIM * DIM;  ga.C[1] = vph;
        ga.B[2] = wth + 3 * DIM * DIM;  ga.C[2] = ksh;
        ga.B[3] = wth + 4 * DIM * DIM;  ga.C[3] = vsh;
        dim3 gm(2, 256 + 64, 2);
        gemm_1t<<<gm, 256, GEMM1_SMEM>>>(ga);

        dim3 gq(2, (N_B * GSM) / 128, 1);
        gemm_2t<<<gq, 256, GEMM2_SMEM>>>(sgh, sgl, wth + 2 * DIM * DIM, qsh);
    }

    // attention
    {
        dim3 ga(NHEAD, N_B);
        attn_tc<<<ga, 256>>>(qsh, kph, vph, ksh, vsh, mp, ms, out);
    }
}